// round 16
// baseline (speedup 1.0000x reference)
#include <cuda_runtime.h>
#include <cuda_fp16.h>
#include <cstdint>

#define BATCH  4
#define SEQ    4096
#define DMODEL 1024
#define HSZ    64
#define NROWS  (BATCH*SEQ)

// Scratch (device globals). Attention-optimized layouts:
//  g_q : [b][t][h] fp16, pre-scaled by log2e/32
//  g_ku: [b][t][u32 x32]  K rows, 8-uint groups permuted [0,4,1,5,2,6,3,7]
//  g_vt: [b][h][tpair u32] V^T pair-packed, same group permutation
//  g_wh: [w][n(64)][u32 x512] W fp16 k-pairs, same group permutation
//  g_ob/g_lb/g_cnt: per-(qtile,slot) partial O/l buffers + arrival counters
__device__ __half   g_q [NROWS*HSZ];
__device__ unsigned g_ku[NROWS*32];
__device__ unsigned g_vt[BATCH*HSZ*(SEQ/2)];
__device__ unsigned g_wh[3*HSZ*512];
__device__ float    g_ob[128*3*128*64];
__device__ float    g_lb[128*3*128];
__device__ int      g_cnt[128];

// ============================ helpers =======================================
static __device__ __forceinline__ unsigned ex2h2(unsigned x){
    unsigned y; asm("ex2.approx.f16x2 %0, %1;" : "=r"(y) : "r"(x)); return y;
}
static __device__ __forceinline__ unsigned h2pk(float lo, float hi){
    unsigned r; asm("cvt.rn.f16x2.f32 %0, %1, %2;" : "=r"(r) : "f"(hi), "f"(lo)); return r;
}
static __device__ __forceinline__ unsigned hadd2u(unsigned a, unsigned b){
    unsigned r; asm("add.f16x2 %0, %1, %2;" : "=r"(r) : "r"(a), "r"(b)); return r;
}
static __device__ __forceinline__ float h2sumf(unsigned x){
    __half2 h = *(__half2*)&x;
    return __low2float(h) + __high2float(h);
}
static __device__ __forceinline__ void mma16(float c[4], const unsigned a[4],
                                             unsigned b0, unsigned b1){
    asm("mma.sync.aligned.m16n8k16.row.col.f32.f16.f16.f32 "
        "{%0,%1,%2,%3}, {%4,%5,%6,%7}, {%8,%9}, {%0,%1,%2,%3};"
        : "+f"(c[0]), "+f"(c[1]), "+f"(c[2]), "+f"(c[3])
        : "r"(a[0]), "r"(a[1]), "r"(a[2]), "r"(a[3]), "r"(b0), "r"(b1));
}
static __device__ __forceinline__ void mma16h(unsigned c[2], const unsigned a[4],
                                              unsigned b0, unsigned b1){
    asm("mma.sync.aligned.m16n8k16.row.col.f16.f16.f16.f16 "
        "{%0,%1}, {%2,%3,%4,%5}, {%6,%7}, {%0,%1};"
        : "+r"(c[0]), "+r"(c[1])
        : "r"(a[0]), "r"(a[1]), "r"(a[2]), "r"(a[3]), "r"(b0), "r"(b1));
}
#define CP_ASYNC16(saddr, gaddr) \
    asm volatile("cp.async.cg.shared.global [%0], [%1], 16;" :: "r"(saddr), "l"(gaddr))
#define CP_COMMIT() asm volatile("cp.async.commit_group;" ::: "memory")
#define CP_WAIT0()  asm volatile("cp.async.wait_group 0;" ::: "memory")

#define QSCALE 0.04508422f        /* log2(e) / 32 */

__device__ __forceinline__ int gperm(int w){ return 2 * (w & 3) + (w >> 2); }
__device__ __forceinline__ int cpos(int p){ return (p & ~7) + gperm(p & 7); }

// flat attention partition: 4096 units over 148 CTAs
__device__ __forceinline__ int part_lo(int i){ return (1024 * i) / 37; }
__device__ __forceinline__ int unit_cta(int u){ return (37 * u + 36) >> 10; }

// ============================================================================
// W pre-convert (grid 384, 1 uint/thread) + attention counter reset.
// ============================================================================
__global__ __launch_bounds__(256, 1) void wcvt_kernel(
    const float* __restrict__ Wq, const float* __restrict__ Wk,
    const float* __restrict__ Wv)
{
    if (blockIdx.x == 0 && threadIdx.x < 128) g_cnt[threadIdx.x] = 0;
    const int i = blockIdx.x * 256 + threadIdx.x;   // 0..98303
    const int w = i >> 15;
    const int rem = i & 32767;
    const int u = rem >> 6;                          // k-pair 0..511
    const int n = rem & 63;
    const float* Wp = (w == 0) ? Wq : (w == 1) ? Wk : Wv;
    float lo = Wp[(size_t)(2 * u)     * HSZ + n];
    float hi = Wp[(size_t)(2 * u + 1) * HSZ + n];
    g_wh[(size_t)(w * 64 + n) * 512 + cpos(u)] = h2pk(lo, hi);
}

// ============================================================================
// Fused fp16 tensor-core projection, cp.async double-buffered. (unchanged)
// ============================================================================
#define XST 72
#define WR_U 40
#define PX_FLOATS (128*XST)
#define PW_UINTS  (192*WR_U)
#define PBUF_UINTS (PX_FLOATS + PW_UINTS)
#define PROJ_SMEM (2 * PBUF_UINTS * 4)

__global__ __launch_bounds__(256, 1) void proj_kernel(
    const float* __restrict__ x)
{
    extern __shared__ unsigned psu[];
    const unsigned smem_u = (unsigned)__cvta_generic_to_shared(psu);

    const int tid  = threadIdx.x;
    const int lane = tid & 31;
    const int wid  = tid >> 5;
    const int mw   = wid & 3;
    const int nw   = wid >> 2;
    const int g    = lane >> 2;
    const int tg   = lane & 3;
    const int rt0  = blockIdx.x * 128;

    float c[2][12][4];
    #pragma unroll
    for (int mi = 0; mi < 2; mi++)
        #pragma unroll
        for (int t = 0; t < 12; t++)
            #pragma unroll
            for (int j = 0; j < 4; j++) c[mi][t][j] = 0.0f;

    #define PROJ_ISSUE(buf_off, kc_) do {                                         \
        const unsigned bo = (buf_off);                                            \
        _Pragma("unroll")                                                         \
        for (int u = 0; u < 8; u++) {                                             \
            const int idx = u * 256 + tid;                                        \
            const int row = idx >> 4, c4 = (idx & 15) * 4;                        \
            CP_ASYNC16(smem_u + bo + (row * XST + c4) * 4,                        \
                       x + (size_t)(rt0 + row) * DMODEL + (kc_) * 64 + c4);       \
        }                                                                         \
        _Pragma("unroll")                                                         \
        for (int u = 0; u < 6; u++) {                                             \
            const int idx = u * 256 + tid;                                        \
            const int row = idx >> 3, q8 = idx & 7;                               \
            CP_ASYNC16(smem_u + bo + (PX_FLOATS + row * WR_U + q8 * 4) * 4,       \
                       g_wh + (size_t)row * 512 + (kc_) * 32 + q8 * 4);           \
        }                                                                         \
        CP_COMMIT();                                                              \
    } while (0)

    PROJ_ISSUE(0, 0);

    for (int kc = 0; kc < 16; kc++) {
        const unsigned* Bu = psu + (kc & 1) * PBUF_UINTS;
        const float*    Xs = (const float*)Bu;
        const unsigned* Ws = Bu + PX_FLOATS;

        CP_WAIT0();
        __syncthreads();
        if (kc + 1 < 16) PROJ_ISSUE(((kc + 1) & 1) * PBUF_UINTS * 4, kc + 1);

        unsigned a[2][4][4];
        #pragma unroll
        for (int mi = 0; mi < 2; mi++) {
            const int r0 = mw * 32 + mi * 16 + g;
            #pragma unroll
            for (int s = 0; s < 4; s++) {
                const int k0 = 16 * s + 2 * tg;
                float2 xa = *(const float2*)&Xs[r0       * XST + k0];
                float2 xb = *(const float2*)&Xs[(r0 + 8) * XST + k0];
                float2 xc = *(const float2*)&Xs[r0       * XST + k0 + 8];
                float2 xd = *(const float2*)&Xs[(r0 + 8) * XST + k0 + 8];
                a[mi][s][0] = h2pk(xa.x, xa.y);
                a[mi][s][1] = h2pk(xb.x, xb.y);
                a[mi][s][2] = h2pk(xc.x, xc.y);
                a[mi][s][3] = h2pk(xd.x, xd.y);
            }
        }
        #pragma unroll
        for (int s = 0; s < 4; s++) {
            #pragma unroll
            for (int t = 0; t < 12; t++) {
                const int gt  = nw * 12 + t;
                const int row = (gt >> 3) * 64 + (gt & 7) * 8 + g;
                unsigned long long kk = *(const unsigned long long*)
                    &Ws[row * WR_U + 8 * s + 2 * tg];
                mma16(c[0][t], a[0][s], (unsigned)kk, (unsigned)(kk >> 32));
                mma16(c[1][t], a[1][s], (unsigned)kk, (unsigned)(kk >> 32));
            }
        }
    }

    #pragma unroll
    for (int t = 0; t < 12; t++) {
        const int gt   = nw * 12 + t;
        const int w    = gt >> 3;
        const int tile = gt & 7;
        const int h0   = tile * 8 + 2 * tg;
        #pragma unroll
        for (int mi = 0; mi < 2; mi++) {
            const int r = rt0 + mw * 32 + mi * 16 + g;
            float v0 = c[mi][t][0], v1 = c[mi][t][1];
            float v2 = c[mi][t][2], v3 = c[mi][t][3];
            if (w == 0) {
                v0 *= QSCALE; v1 *= QSCALE; v2 *= QSCALE; v3 *= QSCALE;
                *(__half2*)&g_q[(size_t)r       * HSZ + h0] = __floats2half2_rn(v0, v1);
                *(__half2*)&g_q[(size_t)(r + 8) * HSZ + h0] = __floats2half2_rn(v2, v3);
            } else if (w == 1) {
                const int col = 8 * (tile >> 1) + 2 * tg + (tile & 1);
                g_ku[(size_t)r       * 32 + col] = h2pk(v0, v1);
                g_ku[(size_t)(r + 8) * 32 + col] = h2pk(v2, v3);
            } else {
                float n0 = __shfl_down_sync(0xFFFFFFFFu, v0, 4);
                float n1 = __shfl_down_sync(0xFFFFFFFFu, v1, 4);
                float n2 = __shfl_down_sync(0xFFFFFFFFu, v2, 4);
                float n3 = __shfl_down_sync(0xFFFFFFFFu, v3, 4);
                if (!(g & 1)) {
                    const size_t vb2 = (size_t)(r >> 12) * HSZ * (SEQ / 2);
                    const int p  = (r & (SEQ - 1)) >> 1;
                    const int c0 = cpos(p), c4 = cpos(p + 4);
                    g_vt[vb2 + (size_t)h0       * (SEQ/2) + c0] = h2pk(v0, n0);
                    g_vt[vb2 + (size_t)(h0 + 1) * (SEQ/2) + c0] = h2pk(v1, n1);
                    g_vt[vb2 + (size_t)h0       * (SEQ/2) + c4] = h2pk(v2, n2);
                    g_vt[vb2 + (size_t)(h0 + 1) * (SEQ/2) + c4] = h2pk(v3, n3);
                }
            }
        }
    }
}

// ============================================================================
// fp16 flash attention, flat-partition persistent form. grid = 148 CTAs.
// 4096 units (qtile 0..127 x kt 0..31); CTA i handles units [U(i), U(i+1)).
// No-max softmax => key-split combine is exact. Last arriver per qtile merges
// the 2-3 segment partials (deterministic slot order) and writes the output.
// ============================================================================
#define KS_U 40
#define VS_U 72
#define KS_UINTS (128*KS_U)
#define VS_UINTS (64*VS_U)
#define BUF_UINTS (KS_UINTS + VS_UINTS)
#define OP_STRIDE 66
#define OPART_OFF (2*BUF_UINTS)                       /* uints */
#define LPART_OFF (OPART_OFF + 128*OP_STRIDE)
#define SFLAG_OFF (LPART_OFF + 128)
#define ATTN_SMEM ((SFLAG_OFF + 8) * 4)

__global__ __launch_bounds__(256, 1) void attn_kernel(float* __restrict__ outp)
{
    extern __shared__ unsigned smu[];
    const unsigned smem_u = (unsigned)__cvta_generic_to_shared(smu);
    float* Opart = (float*)(smu + OPART_OFF);
    float* lpart = (float*)(smu + LPART_OFF);
    int*   sflag = (int*)(smu + SFLAG_OFF);

    const int tid  = threadIdx.x;
    const int lane = tid & 31;
    const int wid  = tid >> 5;
    const int mw   = wid & 3;
    const int nw   = wid >> 2;
    const int g    = lane >> 2;
    const int tg   = lane & 3;

    const int cta  = blockIdx.x;
    const int u_lo = part_lo(cta);
    const int u_hi = part_lo(cta + 1);

    const int k_key = tid >> 1, k_half = tid & 1;
    const int v_row = tid >> 2, v_q    = tid & 3;

    #define ATTN_ISSUE(bufo, u_) do {                                               \
        const int b_ = (u_) >> 10, kt_ = (u_) & 31;                                 \
        const unsigned* kg = g_ku + (size_t)b_ * SEQ * 32                           \
                             + (size_t)(kt_ * 128 + k_key) * 32 + k_half * 16;      \
        const unsigned ksm = smem_u + (bufo) + (k_key * KS_U + k_half * 16) * 4;    \
        _Pragma("unroll")                                                           \
        for (int uu = 0; uu < 4; uu++) CP_ASYNC16(ksm + uu * 16, kg + uu * 4);      \
        const unsigned* vg = g_vt + (size_t)b_ * HSZ * (SEQ/2)                      \
                             + (size_t)v_row * (SEQ/2) + kt_ * 64 + v_q * 16;       \
        const unsigned vsm = smem_u + (bufo)                                        \
                             + (KS_UINTS + v_row * VS_U + v_q * 16) * 4;            \
        _Pragma("unroll")                                                           \
        for (int uu = 0; uu < 4; uu++) CP_ASYNC16(vsm + uu * 16, vg + uu * 4);      \
        CP_COMMIT();                                                                \
    } while (0)

    unsigned qa[2][4][4];
    float o[2][8][4];
    float ls[2][2];
    int cur_q = -1;

    // ---- flush: combine key halves, post/merge this qtile's partial ----
    auto flush = [&](int q){
        __syncthreads();
        if (nw == 1) {
            #pragma unroll
            for (int mi = 0; mi < 2; mi++) {
                const int r0 = mw * 32 + mi * 16 + g;
                #pragma unroll
                for (int nt = 0; nt < 8; nt++) {
                    const int c = nt * 8 + 2 * tg;
                    *(float2*)&Opart[r0       * OP_STRIDE + c] = make_float2(o[mi][nt][0], o[mi][nt][1]);
                    *(float2*)&Opart[(r0 + 8) * OP_STRIDE + c] = make_float2(o[mi][nt][2], o[mi][nt][3]);
                }
                if (tg == 0) {
                    lpart[r0]     = ls[mi][0];
                    lpart[r0 + 8] = ls[mi][1];
                }
            }
        }
        __syncthreads();

        const int first = unit_cta(32 * q);
        const int last  = unit_cta(32 * q + 31);
        const int nseg  = last - first + 1;
        const int ord   = cta - first;

        float of[2][8][4], lf[2][2];
        if (nw == 0) {
            #pragma unroll
            for (int mi = 0; mi < 2; mi++) {
                const int r0 = mw * 32 + mi * 16 + g;
                #pragma unroll
                for (int nt = 0; nt < 8; nt++) {
                    const int c = nt * 8 + 2 * tg;
                    float2 p0 = *(const float2*)&Opart[r0       * OP_STRIDE + c];
                    float2 p1 = *(const float2*)&Opart[(r0 + 8) * OP_STRIDE + c];
                    of[mi][nt][0] = o[mi][nt][0] + p0.x;
                    of[mi][nt][1] = o[mi][nt][1] + p0.y;
                    of[mi][nt][2] = o[mi][nt][2] + p1.x;
                    of[mi][nt][3] = o[mi][nt][3] + p1.y;
                }
                lf[mi][0] = ls[mi][0] + lpart[r0];
                lf[mi][1] = ls[mi][1] + lpart[r0 + 8];
            }
            // post own slot
            float* ob = g_ob + (size_t)(q * 3 + ord) * 128 * 64;
            float* lb = g_lb + (size_t)(q * 3 + ord) * 128;
            #pragma unroll
            for (int mi = 0; mi < 2; mi++) {
                const int r0 = mw * 32 + mi * 16 + g;
                #pragma unroll
                for (int nt = 0; nt < 8; nt++) {
                    const int c = nt * 8 + 2 * tg;
                    *(float2*)&ob[r0       * 64 + c] = make_float2(of[mi][nt][0], of[mi][nt][1]);
                    *(float2*)&ob[(r0 + 8) * 64 + c] = make_float2(of[mi][nt][2], of[mi][nt][3]);
                }
                if (tg == 0) {
                    lb[r0]     = lf[mi][0];
                    lb[r0 + 8] = lf[mi][1];
                }
            }
        }
        __threadfence();
        __syncthreads();
        if (tid == 0) *sflag = atomicAdd(&g_cnt[q], 1);
        __syncthreads();
        const int old = *sflag;

        if (old == nseg - 1 && nw == 0) {
            __threadfence();
            // deterministic sum in slot order (own partial inserted at ord)
            float accO[2][8][4], accL[2][2];
            #pragma unroll
            for (int mi = 0; mi < 2; mi++) {
                #pragma unroll
                for (int nt = 0; nt < 8; nt++)
                    #pragma unroll
                    for (int j = 0; j < 4; j++) accO[mi][nt][j] = 0.0f;
                accL[mi][0] = 0.0f; accL[mi][1] = 0.0f;
            }
            for (int s = 0; s < nseg; s++) {
                if (s == ord) {
                    #pragma unroll
                    for (int mi = 0; mi < 2; mi++) {
                        #pragma unroll
                        for (int nt = 0; nt < 8; nt++)
                            #pragma unroll
                            for (int j = 0; j < 4; j++) accO[mi][nt][j] += of[mi][nt][j];
                        accL[mi][0] += lf[mi][0];
                        accL[mi][1] += lf[mi][1];
                    }
                } else {
                    const float* ob = g_ob + (size_t)(q * 3 + s) * 128 * 64;
                    const float* lb = g_lb + (size_t)(q * 3 + s) * 128;
                    #pragma unroll
                    for (int mi = 0; mi < 2; mi++) {
                        const int r0 = mw * 32 + mi * 16 + g;
                        #pragma unroll
                        for (int nt = 0; nt < 8; nt++) {
                            const int c = nt * 8 + 2 * tg;
                            float2 p0 = *(const float2*)&ob[r0       * 64 + c];
                            float2 p1 = *(const float2*)&ob[(r0 + 8) * 64 + c];
                            accO[mi][nt][0] += p0.x; accO[mi][nt][1] += p0.y;
                            accO[mi][nt][2] += p1.x; accO[mi][nt][3] += p1.y;
                        }
                        accL[mi][0] += lb[r0];
                        accL[mi][1] += lb[r0 + 8];
                    }
                }
            }
            const int b  = q >> 5;
            const int q0 = (q & 31) * 128;
            #pragma unroll
            for (int mi = 0; mi < 2; mi++) {
                const int r0 = mw * 32 + mi * 16 + g;
                const float inv0 = 1.0f / accL[mi][0];
                const float inv1 = 1.0f / accL[mi][1];
                float* ob0 = outp + ((size_t)b * SEQ + q0 + r0) * HSZ;
                float* ob1 = ob0 + 8 * HSZ;
                #pragma unroll
                for (int nt = 0; nt < 8; nt++) {
                    const int c = nt * 8 + 2 * tg;
                    *(float2*)(ob0 + c) = make_float2(accO[mi][nt][0] * inv0,
                                                      accO[mi][nt][1] * inv0);
                    *(float2*)(ob1 + c) = make_float2(accO[mi][nt][2] * inv1,
                                                      accO[mi][nt][3] * inv1);
                }
            }
        }
    };

    ATTN_ISSUE((u_lo & 1) * BUF_UINTS * 4, u_lo);

    for (int u = u_lo; u < u_hi; u++) {
        const int q  = u >> 5;
        const int kt = u & 31;
        (void)kt;
        if (q != cur_q) {
            if (cur_q >= 0) flush(cur_q);
            cur_q = q;
            const int b  = q >> 5;
            const int q0 = (q & 31) * 128;
            const unsigned* qb = (const unsigned*)(g_q + ((size_t)b * SEQ + q0) * HSZ);
            #pragma unroll
            for (int mi = 0; mi < 2; mi++) {
                const int r0 = mw * 32 + mi * 16 + g;
                #pragma unroll
                for (int s = 0; s < 4; s++) {
                    qa[mi][s][0] = qb[(size_t)r0       * 32 + 8 * s + tg];
                    qa[mi][s][1] = qb[(size_t)(r0 + 8) * 32 + 8 * s + tg];
                    qa[mi][s][2] = qb[(size_t)r0       * 32 + 8 * s + tg + 4];
                    qa[mi][s][3] = qb[(size_t)(r0 + 8) * 32 + 8 * s + tg + 4];
                }
            }
            #pragma unroll
            for (int mi = 0; mi < 2; mi++) {
                #pragma unroll
                for (int nt = 0; nt < 8; nt++)
                    #pragma unroll
                    for (int j = 0; j < 4; j++) o[mi][nt][j] = 0.0f;
                ls[mi][0] = 0.0f; ls[mi][1] = 0.0f;
            }
        }

        const unsigned* Ks = smu + (u & 1) * BUF_UINTS;
        const unsigned* Vs = Ks + KS_UINTS;

        CP_WAIT0();
        __syncthreads();
        if (u + 1 < u_hi) ATTN_ISSUE(((u + 1) & 1) * BUF_UINTS * 4, u + 1);

        // ---- S = Q . K^T : f16-accum HMMA ----
        unsigned csh[2][8][2];
        #pragma unroll
        for (int nt = 0; nt < 8; nt++) {
            csh[0][nt][0] = 0u; csh[0][nt][1] = 0u;
            csh[1][nt][0] = 0u; csh[1][nt][1] = 0u;
        }
        #pragma unroll
        for (int s = 0; s < 4; s++) {
            #pragma unroll
            for (int nt = 0; nt < 8; nt++) {
                unsigned long long kk = *(const unsigned long long*)
                    &Ks[(nw * 64 + nt * 8 + g) * KS_U + 8 * s + 2 * tg];
                mma16h(csh[0][nt], qa[0][s], (unsigned)kk, (unsigned)(kk >> 32));
                mma16h(csh[1][nt], qa[1][s], (unsigned)kk, (unsigned)(kk >> 32));
            }
        }

        // ---- softmax (max=0) ----
        unsigned pa[2][8][2];
        #pragma unroll
        for (int mi = 0; mi < 2; mi++)
            #pragma unroll
            for (int nt = 0; nt < 8; nt++) {
                pa[mi][nt][0] = ex2h2(csh[mi][nt][0]);
                pa[mi][nt][1] = ex2h2(csh[mi][nt][1]);
            }

        // ---- lsum via HADD2 tree ----
        #pragma unroll
        for (int mi = 0; mi < 2; mi++)
            #pragma unroll
            for (int r = 0; r < 2; r++) {
                unsigned s01 = hadd2u(pa[mi][0][r], pa[mi][1][r]);
                unsigned s23 = hadd2u(pa[mi][2][r], pa[mi][3][r]);
                unsigned s45 = hadd2u(pa[mi][4][r], pa[mi][5][r]);
                unsigned s67 = hadd2u(pa[mi][6][r], pa[mi][7][r]);
                unsigned sA  = hadd2u(hadd2u(s01, s23), hadd2u(s45, s67));
                float f = h2sumf(sA);
                f += __shfl_xor_sync(0xFFFFFFFFu, f, 1);
                f += __shfl_xor_sync(0xFFFFFFFFu, f, 2);
                ls[mi][r] += f;
            }

        // ---- O += P . V, f32 accum ----
        #pragma unroll
        for (int s = 0; s < 4; s++) {
            unsigned a0[4] = { pa[0][2*s][0], pa[0][2*s][1],
                               pa[0][2*s + 1][0], pa[0][2*s + 1][1] };
            unsigned a1[4] = { pa[1][2*s][0], pa[1][2*s][1],
                               pa[1][2*s + 1][0], pa[1][2*s + 1][1] };
            #pragma unroll
            for (int nt = 0; nt < 8; nt++) {
                unsigned long long vv = *(const unsigned long long*)
                    &Vs[(nt * 8 + g) * VS_U + nw * 32 + 8 * s + 2 * tg];
                mma16(o[0][nt], a0, (unsigned)vv, (unsigned)(vv >> 32));
                mma16(o[1][nt], a1, (unsigned)vv, (unsigned)(vv >> 32));
            }
        }
    }

    flush(cur_q);
}

// ============================================================================
extern "C" void kernel_launch(void* const* d_in, const int* in_sizes, int n_in,
                              void* d_out, int out_size)
{
    (void)in_sizes; (void)n_in; (void)out_size;
    const float* x  = (const float*)d_in[0];
    const float* Wq = (const float*)d_in[1];
    const float* Wk = (const float*)d_in[2];
    const float* Wv = (const float*)d_in[3];
    float* out = (float*)d_out;

    wcvt_kernel<<<384, 256>>>(Wq, Wk, Wv);

    cudaFuncSetAttribute(proj_kernel,
                         cudaFuncAttributeMaxDynamicSharedMemorySize, PROJ_SMEM);
    proj_kernel<<<NROWS / 128, 256, PROJ_SMEM>>>(x);

    cudaFuncSetAttribute(attn_kernel,
                         cudaFuncAttributeMaxDynamicSharedMemorySize, ATTN_SMEM);
    attn_kernel<<<148, 256, ATTN_SMEM>>>(out);
}

// round 17
// speedup vs baseline: 1.4931x; 1.4931x over previous
#include <cuda_runtime.h>
#include <cuda_fp16.h>
#include <cstdint>

#define BATCH  4
#define SEQ    4096
#define DMODEL 1024
#define HSZ    64
#define NROWS  (BATCH*SEQ)

// Scratch (device globals). Attention-optimized layouts:
//  g_q : [b][t][h] fp16, pre-scaled by log2e/32
//  g_ku: [b][t][u32 x32]  K rows, 8-uint groups permuted [0,4,1,5,2,6,3,7]
//  g_vt: [b][h][tpair u32] V^T pair-packed, same group permutation
//  g_wh: [w][n(64)][u32 x512] W fp16 k-pairs, same group permutation
//  g_ob/g_lb: per-(qtile,slot) partial O / l  (merge kernel consumes)
__device__ __half   g_q [NROWS*HSZ];
__device__ unsigned g_ku[NROWS*32];
__device__ unsigned g_vt[BATCH*HSZ*(SEQ/2)];
__device__ unsigned g_wh[3*HSZ*512];
__device__ float    g_ob[128*3*128*64];
__device__ float    g_lb[128*3*128];

// ============================ helpers =======================================
static __device__ __forceinline__ unsigned ex2h2(unsigned x){
    unsigned y; asm("ex2.approx.f16x2 %0, %1;" : "=r"(y) : "r"(x)); return y;
}
static __device__ __forceinline__ unsigned h2pk(float lo, float hi){
    unsigned r; asm("cvt.rn.f16x2.f32 %0, %1, %2;" : "=r"(r) : "f"(hi), "f"(lo)); return r;
}
static __device__ __forceinline__ unsigned hadd2u(unsigned a, unsigned b){
    unsigned r; asm("add.f16x2 %0, %1, %2;" : "=r"(r) : "r"(a), "r"(b)); return r;
}
static __device__ __forceinline__ float h2sumf(unsigned x){
    __half2 h = *(__half2*)&x;
    return __low2float(h) + __high2float(h);
}
static __device__ __forceinline__ void mma16(float c[4], const unsigned a[4],
                                             unsigned b0, unsigned b1){
    asm("mma.sync.aligned.m16n8k16.row.col.f32.f16.f16.f32 "
        "{%0,%1,%2,%3}, {%4,%5,%6,%7}, {%8,%9}, {%0,%1,%2,%3};"
        : "+f"(c[0]), "+f"(c[1]), "+f"(c[2]), "+f"(c[3])
        : "r"(a[0]), "r"(a[1]), "r"(a[2]), "r"(a[3]), "r"(b0), "r"(b1));
}
static __device__ __forceinline__ void mma16h(unsigned c[2], const unsigned a[4],
                                              unsigned b0, unsigned b1){
    asm("mma.sync.aligned.m16n8k16.row.col.f16.f16.f16.f16 "
        "{%0,%1}, {%2,%3,%4,%5}, {%6,%7}, {%0,%1};"
        : "+r"(c[0]), "+r"(c[1])
        : "r"(a[0]), "r"(a[1]), "r"(a[2]), "r"(a[3]), "r"(b0), "r"(b1));
}
#define CP_ASYNC16(saddr, gaddr) \
    asm volatile("cp.async.cg.shared.global [%0], [%1], 16;" :: "r"(saddr), "l"(gaddr))
#define CP_COMMIT() asm volatile("cp.async.commit_group;" ::: "memory")
#define CP_WAIT0()  asm volatile("cp.async.wait_group 0;" ::: "memory")

#define QSCALE 0.04508422f        /* log2(e) / 32 */

__device__ __forceinline__ int gperm(int w){ return 2 * (w & 3) + (w >> 2); }
__device__ __forceinline__ int cpos(int p){ return (p & ~7) + gperm(p & 7); }

// flat attention partition: 4096 units over 148 CTAs (37*4096 = 151552 = 1024*148)
__device__ __forceinline__ int part_lo(int i){ return (1024 * i) / 37; }
__device__ __forceinline__ int unit_cta(int u){ return (37 * u + 36) >> 10; }

// ============================================================================
// W pre-convert: fp32 [1024][64] -> fp16 k-pair uints, permuted K-style layout.
// ============================================================================
__global__ __launch_bounds__(256, 1) void wcvt_kernel(
    const float* __restrict__ Wq, const float* __restrict__ Wk,
    const float* __restrict__ Wv)
{
    const int t0 = blockIdx.x * 256 + threadIdx.x;   // 24576 threads
    #pragma unroll
    for (int step = 0; step < 4; step++) {
        const int i = t0 + step * 24576;             // uint index 0..98303
        const int w = i >> 15;
        const int rem = i & 32767;
        const int u = rem >> 6;                      // k-pair 0..511
        const int n = rem & 63;
        const float* Wp = (w == 0) ? Wq : (w == 1) ? Wk : Wv;
        float lo = Wp[(size_t)(2 * u)     * HSZ + n];
        float hi = Wp[(size_t)(2 * u + 1) * HSZ + n];
        g_wh[(size_t)(w * 64 + n) * 512 + cpos(u)] = h2pk(lo, hi);
    }
}

// ============================================================================
// Fused fp16 tensor-core projection, cp.async double-buffered. (R15 exact)
// ============================================================================
#define XST 72
#define WR_U 40
#define PX_FLOATS (128*XST)
#define PW_UINTS  (192*WR_U)
#define PBUF_UINTS (PX_FLOATS + PW_UINTS)
#define PROJ_SMEM (2 * PBUF_UINTS * 4)

__global__ __launch_bounds__(256, 1) void proj_kernel(
    const float* __restrict__ x)
{
    extern __shared__ unsigned psu[];
    const unsigned smem_u = (unsigned)__cvta_generic_to_shared(psu);

    const int tid  = threadIdx.x;
    const int lane = tid & 31;
    const int wid  = tid >> 5;
    const int mw   = wid & 3;
    const int nw   = wid >> 2;
    const int g    = lane >> 2;
    const int tg   = lane & 3;
    const int rt0  = blockIdx.x * 128;

    float c[2][12][4];
    #pragma unroll
    for (int mi = 0; mi < 2; mi++)
        #pragma unroll
        for (int t = 0; t < 12; t++)
            #pragma unroll
            for (int j = 0; j < 4; j++) c[mi][t][j] = 0.0f;

    #define PROJ_ISSUE(buf_off, kc_) do {                                         \
        const unsigned bo = (buf_off);                                            \
        _Pragma("unroll")                                                         \
        for (int u = 0; u < 8; u++) {                                             \
            const int idx = u * 256 + tid;                                        \
            const int row = idx >> 4, c4 = (idx & 15) * 4;                        \
            CP_ASYNC16(smem_u + bo + (row * XST + c4) * 4,                        \
                       x + (size_t)(rt0 + row) * DMODEL + (kc_) * 64 + c4);       \
        }                                                                         \
        _Pragma("unroll")                                                         \
        for (int u = 0; u < 6; u++) {                                             \
            const int idx = u * 256 + tid;                                        \
            const int row = idx >> 3, q8 = idx & 7;                               \
            CP_ASYNC16(smem_u + bo + (PX_FLOATS + row * WR_U + q8 * 4) * 4,       \
                       g_wh + (size_t)row * 512 + (kc_) * 32 + q8 * 4);           \
        }                                                                         \
        CP_COMMIT();                                                              \
    } while (0)

    PROJ_ISSUE(0, 0);

    for (int kc = 0; kc < 16; kc++) {
        const unsigned* Bu = psu + (kc & 1) * PBUF_UINTS;
        const float*    Xs = (const float*)Bu;
        const unsigned* Ws = Bu + PX_FLOATS;

        CP_WAIT0();
        __syncthreads();
        if (kc + 1 < 16) PROJ_ISSUE(((kc + 1) & 1) * PBUF_UINTS * 4, kc + 1);

        unsigned a[2][4][4];
        #pragma unroll
        for (int mi = 0; mi < 2; mi++) {
            const int r0 = mw * 32 + mi * 16 + g;
            #pragma unroll
            for (int s = 0; s < 4; s++) {
                const int k0 = 16 * s + 2 * tg;
                float2 xa = *(const float2*)&Xs[r0       * XST + k0];
                float2 xb = *(const float2*)&Xs[(r0 + 8) * XST + k0];
                float2 xc = *(const float2*)&Xs[r0       * XST + k0 + 8];
                float2 xd = *(const float2*)&Xs[(r0 + 8) * XST + k0 + 8];
                a[mi][s][0] = h2pk(xa.x, xa.y);
                a[mi][s][1] = h2pk(xb.x, xb.y);
                a[mi][s][2] = h2pk(xc.x, xc.y);
                a[mi][s][3] = h2pk(xd.x, xd.y);
            }
        }
        #pragma unroll
        for (int s = 0; s < 4; s++) {
            #pragma unroll
            for (int t = 0; t < 12; t++) {
                const int gt  = nw * 12 + t;
                const int row = (gt >> 3) * 64 + (gt & 7) * 8 + g;
                unsigned long long kk = *(const unsigned long long*)
                    &Ws[row * WR_U + 8 * s + 2 * tg];
                mma16(c[0][t], a[0][s], (unsigned)kk, (unsigned)(kk >> 32));
                mma16(c[1][t], a[1][s], (unsigned)kk, (unsigned)(kk >> 32));
            }
        }
    }

    #pragma unroll
    for (int t = 0; t < 12; t++) {
        const int gt   = nw * 12 + t;
        const int w    = gt >> 3;
        const int tile = gt & 7;
        const int h0   = tile * 8 + 2 * tg;
        #pragma unroll
        for (int mi = 0; mi < 2; mi++) {
            const int r = rt0 + mw * 32 + mi * 16 + g;
            float v0 = c[mi][t][0], v1 = c[mi][t][1];
            float v2 = c[mi][t][2], v3 = c[mi][t][3];
            if (w == 0) {
                v0 *= QSCALE; v1 *= QSCALE; v2 *= QSCALE; v3 *= QSCALE;
                *(__half2*)&g_q[(size_t)r       * HSZ + h0] = __floats2half2_rn(v0, v1);
                *(__half2*)&g_q[(size_t)(r + 8) * HSZ + h0] = __floats2half2_rn(v2, v3);
            } else if (w == 1) {
                const int col = 8 * (tile >> 1) + 2 * tg + (tile & 1);
                g_ku[(size_t)r       * 32 + col] = h2pk(v0, v1);
                g_ku[(size_t)(r + 8) * 32 + col] = h2pk(v2, v3);
            } else {
                float n0 = __shfl_down_sync(0xFFFFFFFFu, v0, 4);
                float n1 = __shfl_down_sync(0xFFFFFFFFu, v1, 4);
                float n2 = __shfl_down_sync(0xFFFFFFFFu, v2, 4);
                float n3 = __shfl_down_sync(0xFFFFFFFFu, v3, 4);
                if (!(g & 1)) {
                    const size_t vb2 = (size_t)(r >> 12) * HSZ * (SEQ / 2);
                    const int p  = (r & (SEQ - 1)) >> 1;
                    const int c0 = cpos(p), c4 = cpos(p + 4);
                    g_vt[vb2 + (size_t)h0       * (SEQ/2) + c0] = h2pk(v0, n0);
                    g_vt[vb2 + (size_t)(h0 + 1) * (SEQ/2) + c0] = h2pk(v1, n1);
                    g_vt[vb2 + (size_t)h0       * (SEQ/2) + c4] = h2pk(v2, n2);
                    g_vt[vb2 + (size_t)(h0 + 1) * (SEQ/2) + c4] = h2pk(v3, n3);
                }
            }
        }
    }
}

// ============================================================================
// fp16 flash attention, flat partition over 148 CTAs. R15 mainloop unchanged.
// At each qtile boundary the CTA combines its two key-half warps through smem
// and POSTS the partial O/l to gmem slot (q, cta - first(q)). No atomics, no
// in-kernel merge: the merge kernel (launched after) sums slots per qtile.
// ============================================================================
#define KS_U 40
#define VS_U 72
#define KS_UINTS (128*KS_U)
#define VS_UINTS (64*VS_U)
#define BUF_UINTS (KS_UINTS + VS_UINTS)
#define OP_STRIDE 66
#define OPART_OFF (2*BUF_UINTS)
#define LPART_OFF (OPART_OFF + 128*OP_STRIDE)
#define ATTN_SMEM ((LPART_OFF + 128) * 4)

// combine nw halves in smem, then nw==0 warps post partial to gmem slot
#define FLUSH_SEG(qv) do {                                                        \
    __syncthreads();                                                              \
    if (nw == 1) {                                                                \
        _Pragma("unroll")                                                         \
        for (int mi = 0; mi < 2; mi++) {                                          \
            const int r0 = mw * 32 + mi * 16 + g;                                 \
            _Pragma("unroll")                                                     \
            for (int nt = 0; nt < 8; nt++) {                                      \
                const int cc = nt * 8 + 2 * tg;                                   \
                *(float2*)&Opart[r0       * OP_STRIDE + cc] =                     \
                    make_float2(o[mi][nt][0], o[mi][nt][1]);                      \
                *(float2*)&Opart[(r0 + 8) * OP_STRIDE + cc] =                     \
                    make_float2(o[mi][nt][2], o[mi][nt][3]);                      \
            }                                                                     \
            if (tg == 0) {                                                        \
                lpart[r0]     = ls[mi][0];                                        \
                lpart[r0 + 8] = ls[mi][1];                                        \
            }                                                                     \
        }                                                                         \
    }                                                                             \
    __syncthreads();                                                              \
    if (nw == 0) {                                                                \
        const int ord_ = cta - unit_cta(32 * (qv));                               \
        float* ob_ = g_ob + (size_t)((qv) * 3 + ord_) * 128 * 64;                 \
        float* lb_ = g_lb + (size_t)((qv) * 3 + ord_) * 128;                      \
        _Pragma("unroll")                                                         \
        for (int mi = 0; mi < 2; mi++) {                                          \
            const int r0 = mw * 32 + mi * 16 + g;                                 \
            _Pragma("unroll")                                                     \
            for (int nt = 0; nt < 8; nt++) {                                      \
                const int cc = nt * 8 + 2 * tg;                                   \
                float2 p0 = *(const float2*)&Opart[r0       * OP_STRIDE + cc];    \
                float2 p1 = *(const float2*)&Opart[(r0 + 8) * OP_STRIDE + cc];    \
                *(float2*)&ob_[r0       * 64 + cc] =                              \
                    make_float2(o[mi][nt][0] + p0.x, o[mi][nt][1] + p0.y);        \
                *(float2*)&ob_[(r0 + 8) * 64 + cc] =                              \
                    make_float2(o[mi][nt][2] + p1.x, o[mi][nt][3] + p1.y);        \
            }                                                                     \
            if (tg == 0) {                                                        \
                lb_[r0]     = ls[mi][0] + lpart[r0];                              \
                lb_[r0 + 8] = ls[mi][1] + lpart[r0 + 8];                          \
            }                                                                     \
        }                                                                         \
    }                                                                             \
} while (0)

__global__ __launch_bounds__(256, 1) void attn_kernel()
{
    extern __shared__ unsigned smu[];
    const unsigned smem_u = (unsigned)__cvta_generic_to_shared(smu);
    float* Opart = (float*)(smu + OPART_OFF);
    float* lpart = (float*)(smu + LPART_OFF);

    const int tid  = threadIdx.x;
    const int lane = tid & 31;
    const int wid  = tid >> 5;
    const int mw   = wid & 3;
    const int nw   = wid >> 2;
    const int g    = lane >> 2;
    const int tg   = lane & 3;

    const int cta  = blockIdx.x;
    const int u_lo = part_lo(cta);
    const int u_hi = part_lo(cta + 1);

    const int k_key = tid >> 1, k_half = tid & 1;
    const int v_row = tid >> 2, v_q    = tid & 3;

    #define ATTN_ISSUE(bufo, u_) do {                                               \
        const int b_ = (u_) >> 10, kt_ = (u_) & 31;                                 \
        const unsigned* kg = g_ku + (size_t)b_ * SEQ * 32                           \
                             + (size_t)(kt_ * 128 + k_key) * 32 + k_half * 16;      \
        const unsigned ksm = smem_u + (bufo) + (k_key * KS_U + k_half * 16) * 4;    \
        _Pragma("unroll")                                                           \
        for (int uu = 0; uu < 4; uu++) CP_ASYNC16(ksm + uu * 16, kg + uu * 4);      \
        const unsigned* vg = g_vt + (size_t)b_ * HSZ * (SEQ/2)                      \
                             + (size_t)v_row * (SEQ/2) + kt_ * 64 + v_q * 16;       \
        const unsigned vsm = smem_u + (bufo)                                        \
                             + (KS_UINTS + v_row * VS_U + v_q * 16) * 4;            \
        _Pragma("unroll")                                                           \
        for (int uu = 0; uu < 4; uu++) CP_ASYNC16(vsm + uu * 16, vg + uu * 4);      \
        CP_COMMIT();                                                                \
    } while (0)

    unsigned qa[2][4][4];
    float o[2][8][4];
    float ls[2][2];
    int cur_q = -1;

    ATTN_ISSUE((u_lo & 1) * BUF_UINTS * 4, u_lo);

    for (int u = u_lo; u < u_hi; u++) {
        const int q = u >> 5;
        if (q != cur_q) {
            if (cur_q >= 0) FLUSH_SEG(cur_q);
            cur_q = q;
            const int b  = q >> 5;
            const int q0 = (q & 31) * 128;
            const unsigned* qb = (const unsigned*)(g_q + ((size_t)b * SEQ + q0) * HSZ);
            #pragma unroll
            for (int mi = 0; mi < 2; mi++) {
                const int r0 = mw * 32 + mi * 16 + g;
                #pragma unroll
                for (int s = 0; s < 4; s++) {
                    qa[mi][s][0] = qb[(size_t)r0       * 32 + 8 * s + tg];
                    qa[mi][s][1] = qb[(size_t)(r0 + 8) * 32 + 8 * s + tg];
                    qa[mi][s][2] = qb[(size_t)r0       * 32 + 8 * s + tg + 4];
                    qa[mi][s][3] = qb[(size_t)(r0 + 8) * 32 + 8 * s + tg + 4];
                }
            }
            #pragma unroll
            for (int mi = 0; mi < 2; mi++) {
                #pragma unroll
                for (int nt = 0; nt < 8; nt++)
                    #pragma unroll
                    for (int j = 0; j < 4; j++) o[mi][nt][j] = 0.0f;
                ls[mi][0] = 0.0f; ls[mi][1] = 0.0f;
            }
        }

        const unsigned* Ks = smu + (u & 1) * BUF_UINTS;
        const unsigned* Vs = Ks + KS_UINTS;

        CP_WAIT0();
        __syncthreads();
        if (u + 1 < u_hi) ATTN_ISSUE(((u + 1) & 1) * BUF_UINTS * 4, u + 1);

        // ---- S = Q . K^T : f16-accum HMMA ----
        unsigned csh[2][8][2];
        #pragma unroll
        for (int nt = 0; nt < 8; nt++) {
            csh[0][nt][0] = 0u; csh[0][nt][1] = 0u;
            csh[1][nt][0] = 0u; csh[1][nt][1] = 0u;
        }
        #pragma unroll
        for (int s = 0; s < 4; s++) {
            #pragma unroll
            for (int nt = 0; nt < 8; nt++) {
                unsigned long long kk = *(const unsigned long long*)
                    &Ks[(nw * 64 + nt * 8 + g) * KS_U + 8 * s + 2 * tg];
                mma16h(csh[0][nt], qa[0][s], (unsigned)kk, (unsigned)(kk >> 32));
                mma16h(csh[1][nt], qa[1][s], (unsigned)kk, (unsigned)(kk >> 32));
            }
        }

        // ---- softmax (max=0) ----
        unsigned pa[2][8][2];
        #pragma unroll
        for (int mi = 0; mi < 2; mi++)
            #pragma unroll
            for (int nt = 0; nt < 8; nt++) {
                pa[mi][nt][0] = ex2h2(csh[mi][nt][0]);
                pa[mi][nt][1] = ex2h2(csh[mi][nt][1]);
            }

        // ---- lsum via HADD2 tree ----
        #pragma unroll
        for (int mi = 0; mi < 2; mi++)
            #pragma unroll
            for (int r = 0; r < 2; r++) {
                unsigned s01 = hadd2u(pa[mi][0][r], pa[mi][1][r]);
                unsigned s23 = hadd2u(pa[mi][2][r], pa[mi][3][r]);
                unsigned s45 = hadd2u(pa[mi][4][r], pa[mi][5][r]);
                unsigned s67 = hadd2u(pa[mi][6][r], pa[mi][7][r]);
                unsigned sA  = hadd2u(hadd2u(s01, s23), hadd2u(s45, s67));
                float f = h2sumf(sA);
                f += __shfl_xor_sync(0xFFFFFFFFu, f, 1);
                f += __shfl_xor_sync(0xFFFFFFFFu, f, 2);
                ls[mi][r] += f;
            }

        // ---- O += P . V, f32 accum ----
        #pragma unroll
        for (int s = 0; s < 4; s++) {
            unsigned a0[4] = { pa[0][2*s][0], pa[0][2*s][1],
                               pa[0][2*s + 1][0], pa[0][2*s + 1][1] };
            unsigned a1[4] = { pa[1][2*s][0], pa[1][2*s][1],
                               pa[1][2*s + 1][0], pa[1][2*s + 1][1] };
            #pragma unroll
            for (int nt = 0; nt < 8; nt++) {
                unsigned long long vv = *(const unsigned long long*)
                    &Vs[(nt * 8 + g) * VS_U + nw * 32 + 8 * s + 2 * tg];
                mma16(o[0][nt], a0, (unsigned)vv, (unsigned)(vv >> 32));
                mma16(o[1][nt], a1, (unsigned)vv, (unsigned)(vv >> 32));
            }
        }
    }

    FLUSH_SEG(cur_q);
}

// ============================================================================
// Merge: per qtile, sum the 2-3 segment partials in slot order, normalize,
// write output. grid 128 x 256 thr; thread owns (row = tid>>1, 32-col half).
// ============================================================================
__global__ __launch_bounds__(256, 1) void merge_kernel(float* __restrict__ outp)
{
    const int q     = blockIdx.x;
    const int first = unit_cta(32 * q);
    const int last  = unit_cta(32 * q + 31);
    const int nseg  = last - first + 1;

    const int r  = threadIdx.x >> 1;
    const int ch = (threadIdx.x & 1) * 32;

    float acc[32];
    #pragma unroll
    for (int i = 0; i < 32; i++) acc[i] = 0.0f;
    float accL = 0.0f;

    for (int s = 0; s < nseg; s++) {
        const float* ob = g_ob + (size_t)(q * 3 + s) * 128 * 64 + (size_t)r * 64 + ch;
        #pragma unroll
        for (int i = 0; i < 8; i++) {
            float4 v = *(const float4*)(ob + i * 4);
            acc[4*i + 0] += v.x; acc[4*i + 1] += v.y;
            acc[4*i + 2] += v.z; acc[4*i + 3] += v.w;
        }
        accL += g_lb[(size_t)(q * 3 + s) * 128 + r];
    }

    const float inv = 1.0f / accL;
    const int b  = q >> 5;
    const int t  = (q & 31) * 128 + r;
    float* op = outp + ((size_t)b * SEQ + t) * HSZ + ch;
    #pragma unroll
    for (int i = 0; i < 8; i++) {
        float4 w;
        w.x = acc[4*i + 0] * inv; w.y = acc[4*i + 1] * inv;
        w.z = acc[4*i + 2] * inv; w.w = acc[4*i + 3] * inv;
        *(float4*)(op + i * 4) = w;
    }
}

// ============================================================================
extern "C" void kernel_launch(void* const* d_in, const int* in_sizes, int n_in,
                              void* d_out, int out_size)
{
    (void)in_sizes; (void)n_in; (void)out_size;
    const float* x  = (const float*)d_in[0];
    const float* Wq = (const float*)d_in[1];
    const float* Wk = (const float*)d_in[2];
    const float* Wv = (const float*)d_in[3];
    float* out = (float*)d_out;

    wcvt_kernel<<<96, 256>>>(Wq, Wk, Wv);

    cudaFuncSetAttribute(proj_kernel,
                         cudaFuncAttributeMaxDynamicSharedMemorySize, PROJ_SMEM);
    proj_kernel<<<NROWS / 128, 256, PROJ_SMEM>>>(x);

    cudaFuncSetAttribute(attn_kernel,
                         cudaFuncAttributeMaxDynamicSharedMemorySize, ATTN_SMEM);
    attn_kernel<<<148, 256, ATTN_SMEM>>>();

    merge_kernel<<<128, 256>>>(out);
}